// round 1
// baseline (speedup 1.0000x reference)
#include <cuda_runtime.h>

// InvDiff: x[64, 4096, 256] fp32
//   d[b,l,f] = x[b,l+1,f] - x[b,l,f]              (l in [0,4095))
//   y[b,l,f] = x[b,l+1,f] - x[b,0,f]  (l<4094), 0 (l==4094)
// Output = [d flattened | y flattened], 2 * 64*4095*256 floats.

static constexpr int B  = 64;
static constexpr int L  = 4096;
static constexpr int F  = 256;
static constexpr int F4 = F / 4;          // 64 float4 per row
static constexpr int LD = L - 1;          // 4095 output rows

__global__ __launch_bounds__(256)
void invdiff_kernel(const float4* __restrict__ x, float4* __restrict__ out) {
    const int f = threadIdx.x;                                   // 0..63
    const int l = blockIdx.y * blockDim.y + threadIdx.y;         // 0..4095
    const int b = blockIdx.z;
    if (l >= LD) return;

    const int baseIn = b * (L * F4);
    const float4 xl  = x[baseIn + l * F4 + f];
    const float4 xl1 = x[baseIn + (l + 1) * F4 + f];
    const float4 x0  = x[baseIn + f];

    float4 d;
    d.x = xl1.x - xl.x;
    d.y = xl1.y - xl.y;
    d.z = xl1.z - xl.z;
    d.w = xl1.w - xl.w;

    float4 yv;
    if (l < LD - 1) {
        yv.x = xl1.x - x0.x;
        yv.y = xl1.y - x0.y;
        yv.z = xl1.z - x0.z;
        yv.w = xl1.w - x0.w;
    } else {
        yv.x = 0.f; yv.y = 0.f; yv.z = 0.f; yv.w = 0.f;
    }

    const int outIdx = b * (LD * F4) + l * F4 + f;
    const int D      = B * LD * F4;       // float4 count of d block
    out[outIdx]     = d;
    out[D + outIdx] = yv;
}

extern "C" void kernel_launch(void* const* d_in, const int* in_sizes, int n_in,
                              void* d_out, int out_size) {
    const float4* x = (const float4*)d_in[0];
    float4* out = (float4*)d_out;

    dim3 block(F4, 4, 1);                           // 256 threads
    dim3 grid(1, (LD + 3) / 4, B);                  // 1024 x 64 blocks
    invdiff_kernel<<<grid, block>>>(x, out);
}